// round 1
// baseline (speedup 1.0000x reference)
#include <cuda_runtime.h>
#include <cuda_bf16.h>
#include <math.h>

// Problem constants
#define NN 4096
#define DD 4096
#define OO 4096
#define EE 8
#define RR 16
#define ER 128      // E*R
#define GG 9        // E+1

// ---------------- device scratch (no allocations allowed) ----------------
__device__ float g_gates[NN * GG];      // softmax gates per row (base + 8 experts)
__device__ float g_t[NN * ER];          // gated LoRA intermediate t'[n, e*16+r]
__device__ float g_At[DD * ER];         // lora_A transposed to [d][e*16+r]

// ---------------- kernel 1: gate logits + top2 + softmax ----------------
// one warp per row; 9 dot products of length 4096
__global__ void gate_kernel(const float* __restrict__ x,
                            const float* __restrict__ gw)
{
    int warp = (blockIdx.x * blockDim.x + threadIdx.x) >> 5;
    int lane = threadIdx.x & 31;
    if (warp >= NN) return;
    const float* xr = x + (size_t)warp * DD;

    float acc[GG];
#pragma unroll
    for (int c = 0; c < GG; c++) acc[c] = 0.f;

    for (int d = lane; d < DD; d += 32) {
        float xv = xr[d];
#pragma unroll
        for (int c = 0; c < GG; c++)
            acc[c] += xv * gw[c * DD + d];
    }
#pragma unroll
    for (int c = 0; c < GG; c++) {
#pragma unroll
        for (int off = 16; off > 0; off >>= 1)
            acc[c] += __shfl_xor_sync(0xFFFFFFFFu, acc[c], off);
    }

    if (lane == 0) {
        // top-2 over experts (indices 1..8)
        float m1 = -INFINITY, m2 = -INFINITY;
        int i1 = -1, i2 = -1;
#pragma unroll
        for (int c = 1; c < GG; c++) {
            float v = acc[c];
            if (v > m1) { m2 = m1; i2 = i1; m1 = v; i1 = c; }
            else if (v > m2) { m2 = v; i2 = c; }
        }
        float vals[GG];
        vals[0] = acc[0];
#pragma unroll
        for (int c = 1; c < GG; c++)
            vals[c] = (c == i1 || c == i2) ? acc[c] : 0.0f;

        float mx = vals[0];
#pragma unroll
        for (int c = 1; c < GG; c++) mx = fmaxf(mx, vals[c]);
        float s = 0.f;
        float e[GG];
#pragma unroll
        for (int c = 0; c < GG; c++) { e[c] = __expf(vals[c] - mx); s += e[c]; }
        float inv = 1.0f / s;
#pragma unroll
        for (int c = 0; c < GG; c++)
            g_gates[warp * GG + c] = e[c] * inv;
    }
}

// ---------------- kernel 2: transpose lora_A -> [d][e*16+r] ----------------
__global__ void transpose_A_kernel(const float* __restrict__ loraA)
{
    int total = EE * DD * RR;
    for (int i = blockIdx.x * blockDim.x + threadIdx.x; i < total;
         i += gridDim.x * blockDim.x) {
        int e = i / (DD * RR);
        int d = (i / RR) % DD;
        int r = i % RR;
        g_At[d * ER + e * RR + r] = loraA[i];
    }
}

// ---------------- kernel 3: t'[n,c] = gate[n,1+c/16] * sum_d x[n,d]*At[d,c] ----
// tiled GEMM 4096 x 128 x 4096, BM=32, BN=128, BK=16, 256 threads, 4x4/thread
__global__ void loraA_kernel(const float* __restrict__ x)
{
    __shared__ float xs[16][32];    // transposed x tile
    __shared__ float as[16][ER];    // At tile

    int tid  = threadIdx.x;
    int tcol = tid & 31;            // 32 col-groups of 4
    int trow = tid >> 5;            // 8 row-groups of 4
    int rowBase = blockIdx.x * 32;

    float acc[4][4];
#pragma unroll
    for (int i = 0; i < 4; i++)
#pragma unroll
        for (int j = 0; j < 4; j++) acc[i][j] = 0.f;

    for (int k0 = 0; k0 < DD; k0 += 16) {
        // load x tile: 32 rows x 16 k (512 floats), 2 per thread
#pragma unroll
        for (int j = 0; j < 2; j++) {
            int i = tid * 2 + j;
            int row = i >> 4;
            int kk  = i & 15;
            xs[kk][row] = x[(size_t)(rowBase + row) * DD + k0 + kk];
        }
        // load At tile: 16 x 128 = 512 float4, 2 per thread
#pragma unroll
        for (int j = 0; j < 2; j++) {
            int i = tid + j * 256;
            int kk = i >> 5;
            int c4 = i & 31;
            *(float4*)&as[kk][c4 * 4] =
                *(const float4*)&g_At[(size_t)(k0 + kk) * ER + c4 * 4];
        }
        __syncthreads();
#pragma unroll
        for (int kk = 0; kk < 16; kk++) {
            float ra[4], rb[4];
            *(float4*)ra = *(const float4*)&xs[kk][trow * 4];
            *(float4*)rb = *(const float4*)&as[kk][tcol * 4];
#pragma unroll
            for (int i = 0; i < 4; i++)
#pragma unroll
                for (int j = 0; j < 4; j++)
                    acc[i][j] += ra[i] * rb[j];
        }
        __syncthreads();
    }
#pragma unroll
    for (int i = 0; i < 4; i++) {
        int row = rowBase + trow * 4 + i;
#pragma unroll
        for (int j = 0; j < 4; j++) {
            int col = tcol * 4 + j;
            float g = g_gates[row * GG + 1 + (col >> 4)];
            g_t[(size_t)row * ER + col] = g * acc[i][j];
        }
    }
}

// ---------------- kernel 4: main fused GEMM ----------------
// out[n,o] = g0[n]*( x@W + b ) + t' @ B_flat
// BM=BN=128, BK=8, 256 threads, 8x8 per thread
__global__ void main_gemm_kernel(const float* __restrict__ x,
                                 const float* __restrict__ W,
                                 const float* __restrict__ b,
                                 const float* __restrict__ loraB,
                                 float* __restrict__ out)
{
    __shared__ float As[8][128];   // transposed (k, m)
    __shared__ float Bs[8][128];   // (k, n)

    int tid  = threadIdx.x;
    int tcol = tid & 15;           // 16 col groups of 8
    int trow = tid >> 4;           // 16 row groups of 8
    int rowBase = blockIdx.y * 128;
    int colBase = blockIdx.x * 128;

    float acc[8][8];
#pragma unroll
    for (int i = 0; i < 8; i++)
#pragma unroll
        for (int j = 0; j < 8; j++) acc[i][j] = 0.f;

    // ----- main K loop over D -----
    {
        int lrow = tid >> 1;           // 0..127
        int lkq  = (tid & 1) * 4;      // 0 or 4
        int bkk  = tid >> 5;           // 0..7
        int bc4  = (tid & 31) * 4;     // 0..124
        for (int d0 = 0; d0 < DD; d0 += 8) {
            float4 xa = *(const float4*)&x[(size_t)(rowBase + lrow) * DD + d0 + lkq];
            As[lkq + 0][lrow] = xa.x;
            As[lkq + 1][lrow] = xa.y;
            As[lkq + 2][lrow] = xa.z;
            As[lkq + 3][lrow] = xa.w;
            *(float4*)&Bs[bkk][bc4] =
                *(const float4*)&W[(size_t)(d0 + bkk) * OO + colBase + bc4];
            __syncthreads();
#pragma unroll
            for (int kk = 0; kk < 8; kk++) {
                float ra[8], rb[8];
                *(float4*)&ra[0] = *(const float4*)&As[kk][trow * 8];
                *(float4*)&ra[4] = *(const float4*)&As[kk][trow * 8 + 4];
                *(float4*)&rb[0] = *(const float4*)&Bs[kk][tcol * 8];
                *(float4*)&rb[4] = *(const float4*)&Bs[kk][tcol * 8 + 4];
#pragma unroll
                for (int i = 0; i < 8; i++)
#pragma unroll
                    for (int j = 0; j < 8; j++)
                        acc[i][j] += ra[i] * rb[j];
            }
            __syncthreads();
        }
    }

    // ----- apply base gate and bias: acc = g0*(acc + b) -----
    {
        float g0[8], bb[8];
#pragma unroll
        for (int i = 0; i < 8; i++)
            g0[i] = g_gates[(rowBase + trow * 8 + i) * GG + 0];
#pragma unroll
        for (int j = 0; j < 8; j++)
            bb[j] = b[colBase + tcol * 8 + j];
#pragma unroll
        for (int i = 0; i < 8; i++)
#pragma unroll
            for (int j = 0; j < 8; j++)
                acc[i][j] = g0[i] * (acc[i][j] + bb[j]);
    }

    // ----- LoRA K loop over 128 (t' @ B_flat), accumulate unscaled -----
    {
        int lrow = tid >> 1;
        int lkq  = (tid & 1) * 4;
        int bkk  = tid >> 5;
        int bc4  = (tid & 31) * 4;
        for (int c0 = 0; c0 < ER; c0 += 8) {
            float4 ta = *(const float4*)&g_t[(size_t)(rowBase + lrow) * ER + c0 + lkq];
            As[lkq + 0][lrow] = ta.x;
            As[lkq + 1][lrow] = ta.y;
            As[lkq + 2][lrow] = ta.z;
            As[lkq + 3][lrow] = ta.w;
            *(float4*)&Bs[bkk][bc4] =
                *(const float4*)&loraB[(size_t)(c0 + bkk) * OO + colBase + bc4];
            __syncthreads();
#pragma unroll
            for (int kk = 0; kk < 8; kk++) {
                float ra[8], rb[8];
                *(float4*)&ra[0] = *(const float4*)&As[kk][trow * 8];
                *(float4*)&ra[4] = *(const float4*)&As[kk][trow * 8 + 4];
                *(float4*)&rb[0] = *(const float4*)&Bs[kk][tcol * 8];
                *(float4*)&rb[4] = *(const float4*)&Bs[kk][tcol * 8 + 4];
#pragma unroll
                for (int i = 0; i < 8; i++)
#pragma unroll
                    for (int j = 0; j < 8; j++)
                        acc[i][j] += ra[i] * rb[j];
            }
            __syncthreads();
        }
    }

    // ----- store -----
#pragma unroll
    for (int i = 0; i < 8; i++) {
        int row = rowBase + trow * 8 + i;
#pragma unroll
        for (int j = 0; j < 8; j += 4) {
            int col = colBase + tcol * 8 + j;
            float4 v = make_float4(acc[i][j], acc[i][j + 1], acc[i][j + 2], acc[i][j + 3]);
            *(float4*)&out[(size_t)row * OO + col] = v;
        }
    }
}

// ---------------- launcher ----------------
extern "C" void kernel_launch(void* const* d_in, const int* in_sizes, int n_in,
                              void* d_out, int out_size)
{
    const float* x      = (const float*)d_in[0];
    const float* W      = (const float*)d_in[1];
    const float* bias   = (const float*)d_in[2];
    const float* loraA  = (const float*)d_in[3];
    const float* loraB  = (const float*)d_in[4];
    const float* gw     = (const float*)d_in[5];
    // d_in[6] = bvv (unused by the reference computation)
    float* out = (float*)d_out;

    gate_kernel<<<NN / 8, 256>>>(x, gw);
    transpose_A_kernel<<<512, 256>>>(loraA);
    loraA_kernel<<<NN / 32, 256>>>(x);
    main_gemm_kernel<<<dim3(OO / 128, NN / 128), 256>>>(x, W, bias, loraB, out);
}